// round 13
// baseline (speedup 1.0000x reference)
#include <cuda_runtime.h>

// LIF recurrence, float4-vectorized + 8-way chunked over T.
// Each thread owns 4 adjacent d-chains (one float4 lane group):
//   - LDG.128/STG.128: 4x fewer memory instructions & L1tex wavefronts
//   - 4 independent recurrences per thread -> MUFU/FFMA chain pipelines (ILP=4)
// Chunking (balanced): chunk 0 stores t in [0,78); chunk c>=1 stores
// [62c+16, 62c+78) after a 16-step discarded warmup from t=62c.
// Every thread executes exactly 78 steps. Contraction ~0.53/step =>
// seam error ~3e-5 << 1e-3 tolerance (measured ~6e-8 at WARM=16, R12).

#define LIF_B 32
#define LIF_T 512
#define LIF_D 2048
#define D4    (LIF_D / 4)      // 512 float4 per row
#define NCHUNK 8
#define WARM 16
#define LEN0 78                // chunk-0 stored length
#define LENC 62                // chunk 1..7 stored length (78 = 62 + 16 warm)
#define LIF_TH 1.0f
#define UN 2                   // timesteps per batch (each = one float4)

__device__ __forceinline__ float lif_sig(float v) {
    const float e = __expf(LIF_TH - v);
    return __fdividef(1.0f, 1.0f + e);           // sigmoid(v - th)
}

// One LIF step on 4 independent chains. Returns spike vector, updates v.
__device__ __forceinline__ float4 lif_step4(float4& v, const float4 xin) {
    v.x = fmaf(0.5f, v.x, 0.5f * xin.x);
    v.y = fmaf(0.5f, v.y, 0.5f * xin.y);
    v.z = fmaf(0.5f, v.z, 0.5f * xin.z);
    v.w = fmaf(0.5f, v.w, 0.5f * xin.w);
    float4 s;
    s.x = lif_sig(v.x);  s.y = lif_sig(v.y);
    s.z = lif_sig(v.z);  s.w = lif_sig(v.w);
    v.x = fmaf(-v.x, s.x, v.x);
    v.y = fmaf(-v.y, s.y, v.y);
    v.z = fmaf(-v.z, s.z, v.z);
    v.w = fmaf(-v.w, s.w, v.w);
    return s;
}

__global__ void __launch_bounds__(256, 5)
lif_kernel(const float4* __restrict__ x, float4* __restrict__ out) {
    const int gid = blockIdx.x * blockDim.x + threadIdx.x;
    const int d4 = gid & (D4 - 1);             // consecutive threads -> consecutive float4
    const int bc = gid >> 9;                   // D4 = 2^9
    const int c  = bc & (NCHUNK - 1);
    const int b  = bc >> 3;                    // NCHUNK = 2^3

    const size_t base = (size_t)b * LIF_T * D4 + d4;   // float4 index
    const float4* __restrict__ xp = x + base;
    float4* __restrict__ op = out + base;

    float4 v = make_float4(0.f, 0.f, 0.f, 0.f);
    const int t_out0 = c ? (LENC * c + WARM) : 0;
    const int len    = c ? LENC : LEN0;

    // ---- Warmup (chunks 1..7): 16 steps from t = 62c, no stores.
    // c is warp-uniform -> no divergence. Reads mostly L2-hit (seam lines
    // are streamed by the neighbor chunk concurrently).
    if (c != 0) {
        const int tw0 = t_out0 - WARM;
        #pragma unroll
        for (int tb = 0; tb < WARM; tb += 4) {
            float4 xv[4];
            #pragma unroll
            for (int u = 0; u < 4; u++)
                xv[u] = __ldg(xp + (size_t)(tw0 + tb + u) * D4);
            #pragma unroll
            for (int u = 0; u < 4; u++)
                (void)lif_step4(v, xv[u]);
        }
    }

    // ---- Main: triple-buffered prefetch, distance 2 batches of UN=2 steps.
    float4 b0[UN], b1[UN], b2[UN];
    #pragma unroll
    for (int u = 0; u < UN; u++)
        b0[u] = __ldg(xp + (size_t)(t_out0 + u) * D4);
    #pragma unroll
    for (int u = 0; u < UN; u++)
        b1[u] = __ldg(xp + (size_t)(t_out0 + UN + u) * D4);

    for (int tb = 0; tb < len; tb += UN) {
        const int t0 = t_out0 + tb;

        // 1) Prefetch batch tb + 2*UN (predicated at the tail).
        const bool has2 = (tb + 2 * UN < len);
        #pragma unroll
        for (int u = 0; u < UN; u++)
            b2[u] = has2 ? __ldg(xp + (size_t)(t0 + 2 * UN + u) * D4)
                         : make_float4(0.f, 0.f, 0.f, 0.f);

        // 2) Compute current batch (4-way ILP per step), store spikes.
        #pragma unroll
        for (int u = 0; u < UN; u++) {
            const float4 s = lif_step4(v, b0[u]);
            __stcs(op + (size_t)(t0 + u) * D4, s);   // STG.128, streaming
        }

        // 3) Rotate buffers (register moves only).
        #pragma unroll
        for (int u = 0; u < UN; u++) { b0[u] = b1[u]; b1[u] = b2[u]; }
    }
}

extern "C" void kernel_launch(void* const* d_in, const int* in_sizes, int n_in,
                              void* d_out, int out_size) {
    const float4* x = (const float4*)d_in[0];
    float4* out = (float4*)d_out;

    const int n_threads_total = LIF_B * (LIF_D / 4) * NCHUNK;  // 131,072
    const int threads = 256;
    const int blocks = n_threads_total / threads;              // 512
    lif_kernel<<<blocks, threads>>>(x, out);
}

// round 14
// speedup vs baseline: 1.0454x; 1.0454x over previous
#include <cuda_runtime.h>

// LIF recurrence, float2-vectorized + 8-way chunked over T.
// R12 (scalar, NCHUNK=4): LSU-issue-bound (~1 mem op / 5.2 cyc vs 4-5 cyc floor).
// R13 (float4, NCHUNK=8): LSU free but occupancy halved -> latency-bound.
// This kernel: float2 halves memory-instr count (LSU ~45%) while NCHUNK=8
// keeps 262,144 threads = 8192 warps (~78% occ) for latency coverage.
// Balanced chunks: chunk 0 stores t in [0,78); chunk c>=1 stores
// [62c+16, 62c+78) after a 16-step discarded warmup from t=62c.
// Every thread runs exactly 78 steps; seam error ~3e-5 << 1e-3.

#define LIF_B 32
#define LIF_T 512
#define LIF_D 2048
#define D2    (LIF_D / 2)      // 1024 float2 per row
#define NCHUNK 8
#define WARM 16
#define LEN0 78                // chunk-0 stored length
#define LENC 62                // chunk 1..7 stored length (78 = 62 + 16 warm)
#define LIF_TH 1.0f
#define UN 2                   // timesteps per buffer batch

__device__ __forceinline__ float lif_sig(float v) {
    const float e = __expf(LIF_TH - v);
    return __fdividef(1.0f, 1.0f + e);           // sigmoid(v - th)
}

// One LIF step on 2 independent chains. Returns spikes, updates v in place.
__device__ __forceinline__ float2 lif_step2(float2& v, const float2 xin) {
    v.x = fmaf(0.5f, v.x, 0.5f * xin.x);          // leak, tau = 2
    v.y = fmaf(0.5f, v.y, 0.5f * xin.y);
    float2 s;
    s.x = lif_sig(v.x);
    s.y = lif_sig(v.y);
    v.x = fmaf(-v.x, s.x, v.x);                   // soft reset v*(1-s)
    v.y = fmaf(-v.y, s.y, v.y);
    return s;
}

__global__ void __launch_bounds__(256, 7)
lif_kernel(const float2* __restrict__ x, float2* __restrict__ out) {
    const int gid = blockIdx.x * blockDim.x + threadIdx.x;
    const int d2 = gid & (D2 - 1);             // consecutive threads -> consecutive float2
    const int bc = gid >> 10;                  // D2 = 2^10
    const int c  = bc & (NCHUNK - 1);
    const int b  = bc >> 3;                    // NCHUNK = 2^3

    const size_t base = (size_t)b * LIF_T * D2 + d2;   // float2 index
    const float2* __restrict__ xp = x + base;
    float2* __restrict__ op = out + base;

    float2 v = make_float2(0.f, 0.f);
    const int t_out0 = c ? (LENC * c + WARM) : 0;
    const int len    = c ? LENC : LEN0;

    // ---- Warmup (chunks 1..7): 16 steps from t = 62c, no stores.
    // c is warp-uniform -> no divergence. Seam lines are concurrently
    // streamed by the neighbor chunk -> mostly L2 hits.
    if (c != 0) {
        const int tw0 = t_out0 - WARM;
        #pragma unroll
        for (int tb = 0; tb < WARM; tb += 4) {
            float2 xv[4];
            #pragma unroll
            for (int u = 0; u < 4; u++)
                xv[u] = __ldg(xp + (size_t)(tw0 + tb + u) * D2);
            #pragma unroll
            for (int u = 0; u < 4; u++)
                (void)lif_step2(v, xv[u]);
        }
    }

    // ---- Main: triple-buffered prefetch, distance 2 batches of UN=2 steps.
    float2 b0[UN], b1[UN], b2[UN];
    #pragma unroll
    for (int u = 0; u < UN; u++)
        b0[u] = __ldg(xp + (size_t)(t_out0 + u) * D2);
    #pragma unroll
    for (int u = 0; u < UN; u++)
        b1[u] = __ldg(xp + (size_t)(t_out0 + UN + u) * D2);

    for (int tb = 0; tb < len; tb += UN) {
        const int t0 = t_out0 + tb;

        // 1) Prefetch batch tb + 2*UN (predicated at the tail).
        const bool has2 = (tb + 2 * UN < len);
        #pragma unroll
        for (int u = 0; u < UN; u++)
            b2[u] = has2 ? __ldg(xp + (size_t)(t0 + 2 * UN + u) * D2)
                         : make_float2(0.f, 0.f);

        // 2) Compute current batch (2-way ILP per step), store spikes.
        #pragma unroll
        for (int u = 0; u < UN; u++) {
            const float2 s = lif_step2(v, b0[u]);
            __stcs(op + (size_t)(t0 + u) * D2, s);   // STG.64, streaming
        }

        // 3) Rotate buffers (register moves only).
        #pragma unroll
        for (int u = 0; u < UN; u++) { b0[u] = b1[u]; b1[u] = b2[u]; }
    }
}

extern "C" void kernel_launch(void* const* d_in, const int* in_sizes, int n_in,
                              void* d_out, int out_size) {
    const float2* x = (const float2*)d_in[0];
    float2* out = (float2*)d_out;

    const int n_threads_total = LIF_B * (LIF_D / 2) * NCHUNK;  // 262,144
    const int threads = 256;
    const int blocks = n_threads_total / threads;              // 1024
    lif_kernel<<<blocks, threads>>>(x, out);
}

// round 17
// speedup vs baseline: 1.0542x; 1.0084x over previous
#include <cuda_runtime.h>

// LIF recurrence, float2-vectorized + 8-way chunked over T. WARM=8.
// R15 crashed: odd chunk lengths (71/63) with UN=2 stride stored one step
// past the chunk (t=512 OOB). Constraint now explicit: UN | every chunk
// length. L0 + 7*Lc = 512 with both even => L0=Lc=64:
//   chunk c stores exactly t in [64c, 64c+64)
//   chunks 1..7 prepend an 8-step discarded warmup from t=64c-8
// Critical-path cohort: 72 steps (R14: 78, -7.7%). Chunk 0: 64 steps.
// Seam error bound (from R14 measurement + contraction <=0.55/step):
// <=~6e-7 per seam, >1000x under the 1e-3 threshold.

#define LIF_B 32
#define LIF_T 512
#define LIF_D 2048
#define D2    (LIF_D / 2)      // 1024 float2 per row
#define NCHUNK 8
#define WARM 8
#define CLEN 64                // stored steps per chunk (all chunks equal)
#define LIF_TH 1.0f
#define UN 2                   // timesteps per buffer batch; UN | CLEN

__device__ __forceinline__ float lif_sig(float v) {
    const float e = __expf(LIF_TH - v);
    return __fdividef(1.0f, 1.0f + e);           // sigmoid(v - th)
}

// One LIF step on 2 independent chains. Returns spikes, updates v in place.
__device__ __forceinline__ float2 lif_step2(float2& v, const float2 xin) {
    v.x = fmaf(0.5f, v.x, 0.5f * xin.x);          // leak, tau = 2
    v.y = fmaf(0.5f, v.y, 0.5f * xin.y);
    float2 s;
    s.x = lif_sig(v.x);
    s.y = lif_sig(v.y);
    v.x = fmaf(-v.x, s.x, v.x);                   // soft reset v*(1-s)
    v.y = fmaf(-v.y, s.y, v.y);
    return s;
}

__global__ void __launch_bounds__(256, 7)
lif_kernel(const float2* __restrict__ x, float2* __restrict__ out) {
    const int gid = blockIdx.x * blockDim.x + threadIdx.x;
    const int d2 = gid & (D2 - 1);             // consecutive threads -> consecutive float2
    const int bc = gid >> 10;                  // D2 = 2^10
    const int c  = bc & (NCHUNK - 1);
    const int b  = bc >> 3;                    // NCHUNK = 2^3

    const size_t base = (size_t)b * LIF_T * D2 + d2;   // float2 index
    const float2* __restrict__ xp = x + base;
    float2* __restrict__ op = out + base;

    float2 v = make_float2(0.f, 0.f);
    const int t_out0 = c * CLEN;               // stores [t_out0, t_out0 + 64)

    // ---- Warmup (chunks 1..7): 8 steps from t = 64c - 8, no stores.
    // c is warp-uniform -> no divergence. All 8 loads front-batched (MLP=8);
    // seam lines are concurrently streamed by the neighbor chunk -> L2 hits.
    if (c != 0) {
        const int tw0 = t_out0 - WARM;
        float2 xv[WARM];
        #pragma unroll
        for (int u = 0; u < WARM; u++)
            xv[u] = __ldg(xp + (size_t)(tw0 + u) * D2);
        #pragma unroll
        for (int u = 0; u < WARM; u++)
            (void)lif_step2(v, xv[u]);
    }

    // ---- Main: triple-buffered prefetch, distance 2 batches of UN=2 steps.
    // CLEN = 64 is a multiple of UN, so every store index is < t_out0 + 64.
    float2 b0[UN], b1[UN], b2[UN];
    #pragma unroll
    for (int u = 0; u < UN; u++)
        b0[u] = __ldg(xp + (size_t)(t_out0 + u) * D2);
    #pragma unroll
    for (int u = 0; u < UN; u++)
        b1[u] = __ldg(xp + (size_t)(t_out0 + UN + u) * D2);

    for (int tb = 0; tb < CLEN; tb += UN) {
        const int t0 = t_out0 + tb;

        // 1) Prefetch batch tb + 2*UN (predicated at the tail).
        const bool has2 = (tb + 2 * UN < CLEN);
        #pragma unroll
        for (int u = 0; u < UN; u++)
            b2[u] = has2 ? __ldg(xp + (size_t)(t0 + 2 * UN + u) * D2)
                         : make_float2(0.f, 0.f);

        // 2) Compute current batch (2-way ILP per step), store spikes.
        #pragma unroll
        for (int u = 0; u < UN; u++) {
            const float2 s = lif_step2(v, b0[u]);
            __stcs(op + (size_t)(t0 + u) * D2, s);   // STG.64, streaming
        }

        // 3) Rotate buffers (register moves only).
        #pragma unroll
        for (int u = 0; u < UN; u++) { b0[u] = b1[u]; b1[u] = b2[u]; }
    }
}

extern "C" void kernel_launch(void* const* d_in, const int* in_sizes, int n_in,
                              void* d_out, int out_size) {
    const float2* x = (const float2*)d_in[0];
    float2* out = (float2*)d_out;

    const int n_threads_total = LIF_B * (LIF_D / 2) * NCHUNK;  // 262,144
    const int threads = 256;
    const int blocks = n_threads_total / threads;              // 1024
    lif_kernel<<<blocks, threads>>>(x, out);
}